// round 1
// baseline (speedup 1.0000x reference)
#include <cuda_runtime.h>

#define NN   68
#define TPB  128
#define TILE 32

// Packed dual-FMA (Blackwell f32x2) — ptxas never emits this from C++.
__device__ __forceinline__ unsigned long long ffma2(unsigned long long a,
                                                    unsigned long long b,
                                                    unsigned long long c) {
    unsigned long long d;
    asm("fma.rn.f32x2 %0, %1, %2, %3;" : "=l"(d) : "l"(a), "l"(b), "l"(c));
    return d;
}
__device__ __forceinline__ void unpk(unsigned long long v, float &x, float &y) {
    asm("mov.b64 {%0, %1}, %2;" : "=f"(x), "=f"(y) : "l"(v));
}

__global__ __launch_bounds__(TPB, 1)
void nmm_kernel(const float* __restrict__ params,
                const float* __restrict__ C,
                const float* __restrict__ y0,
                float* __restrict__ out,
                int num_steps)
{
    // Double-buffered delayed-E (E_{t-1}) — 16B aligned, 272B per buffer keeps
    // both buffers 16B aligned for LDS.128 broadcast reads.
    __shared__ __align__(16) float ebuf[2][NN];
    // Output staging tile: 33-col pad -> per-step STS stride 33 (conflict-free)
    // and flush reads are row-contiguous (conflict-free, 128B-coalesced STG).
    __shared__ float outbuf[NN][TILE + 1];

    const int tid  = threadIdx.x;
    const int lane = tid & 31;
    const int wid  = tid >> 5;
    const int r    = tid;            // row owned by this thread (r < 68)

    // Broadcast parameter loads (L1-resident after first touch).
    const float tau_e = params[0], tau_i = params[1];
    const float c1 = params[2], c2 = params[3], c3 = params[4], c4 = params[5];
    const float c5 = params[6], P  = params[7], kE = params[8], kI = params[9];
    const float inv_te = 1.0f / tau_e;
    const float inv_ti = 1.0f / tau_i;

    const float AE = 1.3f, THR_E = 4.0f;
    const float AI = 2.0f, THR_I = 3.7f;
    // sigmoid(0, a, thr) = 1/(1+exp(a*thr))
    const float S0E = 1.0f / (1.0f + expf(AE * THR_E));
    const float S0I = 1.0f / (1.0f + expf(AI * THR_I));

    float E = 0.0f, I = 0.0f;
    unsigned long long crow[34];     // C row as 34 packed f32x2 (68 regs)

    if (r < NN) {
        E = y0[r];
        I = y0[NN + r];
        ebuf[0][r] = E;              // initial E_prev = y0[:N]
        // C row base = r*272 bytes -> 16B aligned, load as ulonglong2.
        const ulonglong2* cp = reinterpret_cast<const ulonglong2*>(C + r * NN);
        #pragma unroll
        for (int j = 0; j < 17; j++) {
            ulonglong2 c = cp[j];
            crow[2 * j]     = c.x;
            crow[2 * j + 1] = c.y;
        }
    }
    __syncthreads();

    for (int t = 0; t < num_steps; t++) {
        const int cur = t & 1;
        if (r < NN) {
            // conn_r = sum_j C[r][j] * E_prev[j]  (broadcast LDS.128, FFMA2)
            const ulonglong2* eb =
                reinterpret_cast<const ulonglong2*>(ebuf[cur]);
            unsigned long long a0 = 0ull, a1 = 0ull;   // {0.f,0.f} bit pattern
            #pragma unroll
            for (int j = 0; j < 17; j++) {
                ulonglong2 e = eb[j];
                a0 = ffma2(crow[2 * j],     e.x, a0);
                a1 = ffma2(crow[2 * j + 1], e.y, a1);
            }
            float s0x, s0y, s1x, s1y;
            unpk(a0, s0x, s0y);
            unpk(a1, s1x, s1y);
            const float conn = (s0x + s1x) + (s0y + s1y);

            // Stash pre-update E for next step's matvec (other buffer).
            ebuf[cur ^ 1][r] = E;

            // Pointwise Wilson-Cowan update.
            const float xe = c1 * E - c2 * I + c5 * conn + P;
            const float xi = c3 * E - c4 * I;            // Q = 0
            // exp(-a*(x-thr)) == exp(a*(thr-x))  (bit-identical in FP)
            const float se = 1.0f / (1.0f + expf(AE * (THR_E - xe))) - S0E;
            const float si = 1.0f / (1.0f + expf(AI * (THR_I - xi))) - S0I;
            const float En = E + (-E + (kE - E) * se) * inv_te;  // rE = 1
            const float In = I + (-I + (kI - I) * si) * inv_ti;  // rI = 1, DT = 1

            outbuf[r][t & (TILE - 1)] = En - In;   // traj stores post-update y
            E = En;
            I = In;
        }
        __syncthreads();

        // Coalesced flush every TILE steps (and at the tail).
        if (((t & (TILE - 1)) == (TILE - 1)) || (t == num_steps - 1)) {
            const int base = t & ~(TILE - 1);
            const int cnt  = t - base + 1;
            for (int row = wid; row < NN; row += (TPB / 32)) {
                if (lane < cnt)
                    out[row * num_steps + base + lane] = outbuf[row][lane];
            }
            __syncthreads();
        }
    }
}

extern "C" void kernel_launch(void* const* d_in, const int* in_sizes, int n_in,
                              void* d_out, int out_size)
{
    const float* params = (const float*)d_in[0];
    const float* Cjk    = (const float*)d_in[1];
    const float* y0     = (const float*)d_in[2];
    // d_in[3] = Djk: unused by the reference computation.
    float* out = (float*)d_out;
    const int num_steps = out_size / NN;   // out is (N=68, num_steps)
    nmm_kernel<<<1, TPB>>>(params, Cjk, y0, out, num_steps);
}

// round 4
// speedup vs baseline: 1.4429x; 1.4429x over previous
#include <cuda_runtime.h>
#include <math.h>

#define NN   68
#define TPB  128
#define TILE 32

typedef unsigned long long u64;

// Packed dual-FMA / dual-ADD (Blackwell f32x2) — only reachable via PTX.
__device__ __forceinline__ u64 ffma2(u64 a, u64 b, u64 c) {
    u64 d;
    asm("fma.rn.f32x2 %0, %1, %2, %3;" : "=l"(d) : "l"(a), "l"(b), "l"(c));
    return d;
}
__device__ __forceinline__ u64 fadd2(u64 a, u64 b) {
    u64 d;
    asm("add.rn.f32x2 %0, %1, %2;" : "=l"(d) : "l"(a), "l"(b));
    return d;
}
__device__ __forceinline__ void unpk(u64 v, float &x, float &y) {
    asm("mov.b64 {%0, %1}, %2;" : "=f"(x), "=f"(y) : "l"(v));
}
// MUFU fast paths (err ~1e-7 relative; dynamics are strongly contracting —
// R1 tracked the reference to 4e-9 despite a different summation order).
__device__ __forceinline__ float ex2a(float x) {
    float y; asm("ex2.approx.f32 %0, %1;" : "=f"(y) : "f"(x)); return y;
}
__device__ __forceinline__ float rcpa(float x) {
    float y; asm("rcp.approx.f32 %0, %1;" : "=f"(y) : "f"(x)); return y;
}

__global__ __launch_bounds__(TPB, 1)
void nmm_kernel(const float* __restrict__ params,
                const float* __restrict__ C,
                const float* __restrict__ y0,
                float* __restrict__ out,
                int num_steps)
{
    // Double-buffered delayed-E (16B aligned for LDS.128 broadcast).
    __shared__ __align__(16) float ebuf[2][NN];
    // Ping-pong output staging tiles: flush of one overlaps writes of the other
    // (no second barrier). 33-col pad -> conflict-free STS and flush LDS.
    __shared__ float outbuf[2][NN][TILE + 1];

    const int tid  = threadIdx.x;
    const int lane = tid & 31;
    const int wid  = tid >> 5;
    const int r    = tid;                 // row owned by this thread (r < 68)

    const float tau_e = params[0], tau_i = params[1];
    const float c1 = params[2], c2 = params[3], c3 = params[4], c4 = params[5];
    const float c5 = params[6], P  = params[7], kE = params[8], kI = params[9];
    const float inv_te = 1.0f / tau_e;
    const float inv_ti = 1.0f / tau_i;
    const float ce = 1.0f - inv_te;       // En = E*ce + gE*(sigE - S0E)
    const float ci = 1.0f - inv_ti;

    const float LOG2E = 1.4426950408889634f;
    const float AE = 1.3f, THR_E = 4.0f;
    const float AI = 2.0f, THR_I = 3.7f;
    const float aeL = AE * LOG2E;
    const float aiL = AI * LOG2E;
    // Accurate (host-grade) sigmoid-at-0 offsets, computed once.
    const float S0E = 1.0f / (1.0f + expf(AE * THR_E));
    const float S0I = 1.0f / (1.0f + expf(AI * THR_I));

    // One-FMA argument forms:
    //  argE = aeL*(THR_E - xe) = [cE0 + mEc1*E + pEc2*I] + kconn*conn
    //  argI = aiL*(THR_I - xi) =  cI0 + mIc3*E + pIc4*I          (Q = 0)
    const float cE0   = aeL * (THR_E - P);
    const float mEc1  = -aeL * c1;
    const float pEc2  =  aeL * c2;
    const float kconn = -aeL * c5;
    const float cI0   = aiL * THR_I;
    const float mIc3  = -aiL * c3;
    const float pIc4  =  aiL * c4;

    float E = 0.0f, I = 0.0f;
    u64 crow[34];                          // C row: 34 packed f32x2 (68 regs)

    if (r < NN) {
        E = y0[r];
        I = y0[NN + r];
        ebuf[0][r] = E;                    // initial E_prev = y0[:N]
        const ulonglong2* cp = reinterpret_cast<const ulonglong2*>(C + r * NN);
        #pragma unroll
        for (int j = 0; j < 17; j++) {
            ulonglong2 c = cp[j];
            crow[2 * j]     = c.x;
            crow[2 * j + 1] = c.y;
        }
    }
    __syncthreads();

    // ---- one Euler step; CUR = compile-time parity of the ebuf buffers ----
#define STEP_BODY(CUR, T)                                                      \
    {                                                                          \
        if (r < NN) {                                                          \
            /* Everything below until 'conn' depends only on old (E, I):   */  \
            /* issues early and overlaps the matvec.                       */  \
            const float gE = inv_te * (kE - E);                                \
            const float hE = fmaf(-gE, S0E, E * ce);                           \
            const float gI = inv_ti * (kI - I);                                \
            const float hI = fmaf(-gI, S0I, I * ci);                           \
            const float base_e = fmaf(mEc1, E, fmaf(pEc2, I, cE0));            \
            const float argI   = fmaf(mIc3, E, fmaf(pIc4, I, cI0));            \
            const float sI = rcpa(1.0f + ex2a(argI));                          \
            const float In = fmaf(gI, sI, hI);         /* fully off-path  */   \
                                                                               \
            /* DELAYED coupling: next step's matvec must see THIS step's   */  \
            /* PRE-update E (reference scan carries y_t[:N]).              */  \
            ebuf[(CUR) ^ 1][r] = E;                                            \
                                                                               \
            /* conn_r = C[r,:] . E_prev  — 4 chains, packed reduce */          \
            const ulonglong2* eb =                                             \
                reinterpret_cast<const ulonglong2*>(ebuf[CUR]);                \
            u64 a0 = 0ull, a1 = 0ull, a2 = 0ull, a3 = 0ull;                    \
            _Pragma("unroll")                                                  \
            for (int j = 0; j < 17; j++) {                                     \
                ulonglong2 e = eb[j];                                          \
                if (j & 1) {                                                   \
                    a2 = ffma2(crow[2 * j],     e.x, a2);                      \
                    a3 = ffma2(crow[2 * j + 1], e.y, a3);                      \
                } else {                                                       \
                    a0 = ffma2(crow[2 * j],     e.x, a0);                      \
                    a1 = ffma2(crow[2 * j + 1], e.y, a1);                      \
                }                                                              \
            }                                                                  \
            u64 s = fadd2(fadd2(a0, a1), fadd2(a2, a3));                       \
            float sx, sy;                                                      \
            unpk(s, sx, sy);                                                   \
            const float conn = sx + sy;                                        \
                                                                               \
            /* Critical path: 1 FMA -> EX2 -> FADD -> RCP -> FMA -> STS */     \
            const float argE = fmaf(kconn, conn, base_e);                      \
            const float sE   = rcpa(1.0f + ex2a(argE));                        \
            const float En   = fmaf(gE, sE, hE);                               \
            outbuf[((T) >> 5) & 1][r][(T) & (TILE - 1)] = En - In;             \
            E = En;                                                            \
            I = In;                                                            \
        }                                                                      \
        __syncthreads();                                                       \
        if (((T) & (TILE - 1)) == (TILE - 1)) {                                \
            /* Flush the just-completed tile; overlaps the next 32 steps   */  \
            /* which write the other tile — no extra barrier needed.       */  \
            const int tile = ((T) >> 5) & 1;                                   \
            const int base = (T) - (TILE - 1);                                 \
            for (int row = wid; row < NN; row += (TPB / 32))                   \
                out[row * num_steps + base + lane] = outbuf[tile][row][lane];  \
        }                                                                      \
    }

    int t = 0;
    const int n2 = num_steps & ~1;
    for (; t < n2; t += 2) {
        STEP_BODY(0, t)
        STEP_BODY(1, t + 1)
    }
    if (t < num_steps) {
        STEP_BODY(0, t)
        t++;
    }

    // Tail flush for a partial final tile (num_steps % 32 != 0).
    const int rem = num_steps & (TILE - 1);
    if (rem) {
        const int tile = ((num_steps - 1) >> 5) & 1;
        const int base = num_steps - rem;
        for (int row = wid; row < NN; row += (TPB / 32))
            if (lane < rem)
                out[row * num_steps + base + lane] = outbuf[tile][row][lane];
    }
#undef STEP_BODY
}

extern "C" void kernel_launch(void* const* d_in, const int* in_sizes, int n_in,
                              void* d_out, int out_size)
{
    const float* params = (const float*)d_in[0];
    const float* Cjk    = (const float*)d_in[1];
    const float* y0     = (const float*)d_in[2];
    // d_in[3] = Djk: unused by the reference computation.
    float* out = (float*)d_out;
    const int num_steps = out_size / NN;   // out is (N=68, num_steps)
    nmm_kernel<<<1, TPB>>>(params, Cjk, y0, out, num_steps);
}

// round 5
// speedup vs baseline: 1.5841x; 1.0978x over previous
#include <cuda_runtime.h>
#include <math.h>

#define NN    68
#define TPB   128
#define TILE  32
#define NPRE  10    // ulonglong2 chunks of E_prev prefetched into regs (40 floats)

typedef unsigned long long u64;

// Packed f32x2 ops (Blackwell) — only reachable via PTX.
__device__ __forceinline__ u64 ffma2(u64 a, u64 b, u64 c) {
    u64 d;
    asm("fma.rn.f32x2 %0, %1, %2, %3;" : "=l"(d) : "l"(a), "l"(b), "l"(c));
    return d;
}
__device__ __forceinline__ u64 fadd2(u64 a, u64 b) {
    u64 d;
    asm("add.rn.f32x2 %0, %1, %2;" : "=l"(d) : "l"(a), "l"(b));
    return d;
}
__device__ __forceinline__ u64 fmul2(u64 a, u64 b) {
    u64 d;
    asm("mul.rn.f32x2 %0, %1, %2;" : "=l"(d) : "l"(a), "l"(b));
    return d;
}
__device__ __forceinline__ void unpk(u64 v, float &x, float &y) {
    asm("mov.b64 {%0, %1}, %2;" : "=f"(x), "=f"(y) : "l"(v));
}
__device__ __forceinline__ u64 pack2(float x, float y) {
    u64 v;
    asm("mov.b64 %0, {%1, %2};" : "=l"(v) : "f"(x), "f"(y));
    return v;
}
// MUFU fast paths (~1e-7 rel err; validated: 1.3e-6 final in R4).
__device__ __forceinline__ float ex2a(float x) {
    float y; asm("ex2.approx.f32 %0, %1;" : "=f"(y) : "f"(x)); return y;
}
__device__ __forceinline__ float rcpa(float x) {
    float y; asm("rcp.approx.f32 %0, %1;" : "=f"(y) : "f"(x)); return y;
}

__global__ __launch_bounds__(TPB, 1)
void nmm_kernel(const float* __restrict__ params,
                const float* __restrict__ C,
                const float* __restrict__ y0,
                float* __restrict__ out,
                int num_steps)
{
    // 3-buffer delayed-E rotation: matvec at step s reads ebuf[s%3]; the tail
    // of step s writes E_{s+1} into ebuf[(s+2)%3] (consumed at step s+2).
    // Rows padded to 72 floats so every buffer is 16B aligned for LDS.128.
    __shared__ __align__(16) float ebuf[3][72];
    // Ping-pong output staging tiles (33-col pad: conflict-free).
    __shared__ float outbuf[2][NN][TILE + 1];

    const int tid  = threadIdx.x;
    const int lane = tid & 31;
    const int wid  = tid >> 5;
    const int r    = tid;                 // row owned by this thread (r < 68)

    const float tau_e = params[0], tau_i = params[1];
    const float c1 = params[2], c2 = params[3], c3 = params[4], c4 = params[5];
    const float c5 = params[6], P  = params[7], kE = params[8], kI = params[9];
    const float inv_te = 1.0f / tau_e;
    const float inv_ti = 1.0f / tau_i;
    const float ce = 1.0f - inv_te;
    const float ci = 1.0f - inv_ti;

    const float LOG2E = 1.4426950408889634f;
    const float AE = 1.3f, THR_E = 4.0f;
    const float AI = 2.0f, THR_I = 3.7f;
    const float aeL = AE * LOG2E;
    const float aiL = AI * LOG2E;
    const float S0E = 1.0f / (1.0f + expf(AE * THR_E));
    const float S0I = 1.0f / (1.0f + expf(AI * THR_I));

    // argE = [cE0 + mEc1*E + pEc2*I] + kconn*conn ; argI = cI0 + mIc3*E + pIc4*I
    const float cE0   = aeL * (THR_E - P);
    const float mEc1  = -aeL * c1;
    const float pEc2  =  aeL * c2;
    const float kconn = -aeL * c5;        // folded into crow below
    const float cI0   = aiL * THR_I;
    const float mIc3  = -aiL * c3;
    const float pIc4  =  aiL * c4;

    float E = 0.0f, I = 0.0f;
    u64 crow[34];                         // kconn * C[r,:], packed f32x2
    u64 ep[2 * NPRE];                     // prefetched E_prev chunks 0..NPRE-1

    if (r < NN) {
        E = y0[r];
        I = y0[NN + r];
        ebuf[0][r] = E;                   // steps 0 AND 1 both read E0
        ebuf[1][r] = E;
        const ulonglong2* cp = reinterpret_cast<const ulonglong2*>(C + r * NN);
        const u64 k2 = pack2(kconn, kconn);
        #pragma unroll
        for (int j = 0; j < 17; j++) {
            ulonglong2 c = cp[j];
            crow[2 * j]     = fmul2(c.x, k2);
            crow[2 * j + 1] = fmul2(c.y, k2);
        }
    }
    __syncthreads();

    if (r < NN) {                         // prologue prefetch for step 0
        const ulonglong2* eb = reinterpret_cast<const ulonglong2*>(ebuf[0]);
        #pragma unroll
        for (int j = 0; j < NPRE; j++) {
            ulonglong2 e = eb[j];
            ep[2 * j]     = e.x;
            ep[2 * j + 1] = e.y;
        }
    }

    // ---- one Euler step; PHI = s % 3 (compile-time), S = runtime step ----
#define STEP(PHI, S)                                                           \
    {                                                                          \
        if (r < NN) {                                                          \
            /* front-batch the non-prefetched chunks (consumed after ~40cy) */ \
            const ulonglong2* ebc =                                            \
                reinterpret_cast<const ulonglong2*>(ebuf[(PHI)]);              \
            const ulonglong2 t10 = ebc[10], t11 = ebc[11], t12 = ebc[12],      \
                             t13 = ebc[13], t14 = ebc[14], t15 = ebc[15],      \
                             t16 = ebc[16];                                    \
            /* hoisted pointwise (depends only on old E, I) */                 \
            const float gE = inv_te * (kE - E);                                \
            const float hE = fmaf(-gE, S0E, E * ce);                           \
            const float gI = inv_ti * (kI - I);                                \
            const float hI = fmaf(-gI, S0I, I * ci);                           \
            const float base_e = fmaf(mEc1, E, fmaf(pEc2, I, cE0));            \
            const float argI   = fmaf(mIc3, E, fmaf(pIc4, I, cI0));            \
            const float sIv = rcpa(1.0f + ex2a(argI));                         \
            const float In  = fmaf(gI, sIv, hI);                               \
            /* matvec: chunks 0..NPRE-1 from regs, rest from fresh loads */    \
            u64 a0 = pack2(base_e, 0.0f);   /* seed base_e into reduction */   \
            u64 a1 = 0ull, a2 = 0ull, a3 = 0ull;                               \
            _Pragma("unroll")                                                  \
            for (int j = 0; j < NPRE; j++) {                                   \
                if (j & 1) {                                                   \
                    a2 = ffma2(crow[2 * j],     ep[2 * j],     a2);            \
                    a3 = ffma2(crow[2 * j + 1], ep[2 * j + 1], a3);            \
                } else {                                                       \
                    a0 = ffma2(crow[2 * j],     ep[2 * j],     a0);            \
                    a1 = ffma2(crow[2 * j + 1], ep[2 * j + 1], a1);            \
                }                                                              \
            }                                                                  \
            a0 = ffma2(crow[20], t10.x, a0); a1 = ffma2(crow[21], t10.y, a1);  \
            a2 = ffma2(crow[22], t11.x, a2); a3 = ffma2(crow[23], t11.y, a3);  \
            a0 = ffma2(crow[24], t12.x, a0); a1 = ffma2(crow[25], t12.y, a1);  \
            a2 = ffma2(crow[26], t13.x, a2); a3 = ffma2(crow[27], t13.y, a3);  \
            a0 = ffma2(crow[28], t14.x, a0); a1 = ffma2(crow[29], t14.y, a1);  \
            a2 = ffma2(crow[30], t15.x, a2); a3 = ffma2(crow[31], t15.y, a3);  \
            a0 = ffma2(crow[32], t16.x, a0); a1 = ffma2(crow[33], t16.y, a1);  \
            /* prefetch NEXT step's buffer (fills MUFU-stall slots; data   */  \
            /* was completed at tail of step S-1, ordered by this step's   */  \
            /* entry barrier) */                                               \
            {                                                                  \
                const ulonglong2* ebn =                                        \
                    reinterpret_cast<const ulonglong2*>(ebuf[((PHI) + 1) % 3]);\
                _Pragma("unroll")                                              \
                for (int j = 0; j < NPRE; j++) {                               \
                    ulonglong2 e = ebn[j];                                     \
                    ep[2 * j]     = e.x;                                       \
                    ep[2 * j + 1] = e.y;                                       \
                }                                                              \
            }                                                                  \
            /* reduce (base_e already inside) + sigmoid tail */                \
            u64 sv = fadd2(fadd2(a0, a1), fadd2(a2, a3));                      \
            float sx, sy;                                                      \
            unpk(sv, sx, sy);                                                  \
            const float argE = sx + sy;                                        \
            const float sEv  = rcpa(1.0f + ex2a(argE));                        \
            const float En   = fmaf(gE, sEv, hE);                              \
            ebuf[((PHI) + 2) % 3][r] = En;     /* E_{S+1}, read at step S+2 */ \
            outbuf[((S) >> 5) & 1][r][(S) & (TILE - 1)] = En - In;             \
            E = En;                                                            \
            I = In;                                                            \
        }                                                                      \
        __syncthreads();                                                       \
        /* warp 3 (otherwise idle): flush previous tile, 17 rows per step   */ \
        /* over the 4 steps after tile completion — hidden under step time. */ \
        if (wid == 3) {                                                        \
            const int fk = (S) & 31;                                           \
            if (fk < 4 && (S) >= 32) {                                         \
                const int fb    = ((S) >> 5) - 1;                              \
                const int ftile = fb & 1;                                      \
                const int fbase = fb << 5;                                     \
                _Pragma("unroll")                                              \
                for (int i = 0; i < 17; i++) {                                 \
                    const int row = fk * 17 + i;                               \
                    out[row * num_steps + fbase + lane] =                      \
                        outbuf[ftile][row][lane];                              \
                }                                                              \
            }                                                                  \
        }                                                                      \
    }

    int s = 0;
    for (; s + 3 <= num_steps; s += 3) {
        STEP(0, s)
        STEP(1, s + 1)
        STEP(2, s + 2)
    }
    if (s < num_steps) { STEP(0, s) s++; }
    if (s < num_steps) { STEP(1, s) s++; }
#undef STEP

    // Epilogue: flush whatever the in-loop warp-3 flush couldn't cover
    // (last complete tile whose flush window fell off the end + partial tile).
    int start;
    if (num_steps < 36) start = 0;
    else                start = (((num_steps - 36) >> 5) << 5) + 32;
    for (int tb = start; tb < num_steps; tb += 32) {
        const int ftile = (tb >> 5) & 1;
        const int cnt   = num_steps - tb < 32 ? num_steps - tb : 32;
        for (int row = wid; row < NN; row += 4)
            if (lane < cnt)
                out[row * num_steps + tb + lane] = outbuf[ftile][row][lane];
    }
}

extern "C" void kernel_launch(void* const* d_in, const int* in_sizes, int n_in,
                              void* d_out, int out_size)
{
    const float* params = (const float*)d_in[0];
    const float* Cjk    = (const float*)d_in[1];
    const float* y0     = (const float*)d_in[2];
    // d_in[3] = Djk: unused by the reference computation.
    float* out = (float*)d_out;
    const int num_steps = out_size / NN;   // out is (N=68, num_steps)
    nmm_kernel<<<1, TPB>>>(params, Cjk, y0, out, num_steps);
}

// round 6
// speedup vs baseline: 1.7797x; 1.1235x over previous
#include <cuda_runtime.h>
#include <math.h>

#define NN    68
#define TPB   128
#define TILE  32
#define NPRE  17    // ALL ulonglong2 chunks of E_prev prefetched into regs (68 floats)

typedef unsigned long long u64;

// Packed f32x2 ops (Blackwell) — only reachable via PTX.
__device__ __forceinline__ u64 ffma2(u64 a, u64 b, u64 c) {
    u64 d;
    asm("fma.rn.f32x2 %0, %1, %2, %3;" : "=l"(d) : "l"(a), "l"(b), "l"(c));
    return d;
}
__device__ __forceinline__ u64 fadd2(u64 a, u64 b) {
    u64 d;
    asm("add.rn.f32x2 %0, %1, %2;" : "=l"(d) : "l"(a), "l"(b));
    return d;
}
__device__ __forceinline__ u64 fmul2(u64 a, u64 b) {
    u64 d;
    asm("mul.rn.f32x2 %0, %1, %2;" : "=l"(d) : "l"(a), "l"(b));
    return d;
}
__device__ __forceinline__ void unpk(u64 v, float &x, float &y) {
    asm("mov.b64 {%0, %1}, %2;" : "=f"(x), "=f"(y) : "l"(v));
}
__device__ __forceinline__ u64 pack2(float x, float y) {
    u64 v;
    asm("mov.b64 %0, {%1, %2};" : "=l"(v) : "f"(x), "f"(y));
    return v;
}
// MUFU fast paths (~1e-7 rel err; validated: 1.3e-6 final across 200k steps).
__device__ __forceinline__ float ex2a(float x) {
    float y; asm("ex2.approx.f32 %0, %1;" : "=f"(y) : "f"(x)); return y;
}
__device__ __forceinline__ float rcpa(float x) {
    float y; asm("rcp.approx.f32 %0, %1;" : "=f"(y) : "f"(x)); return y;
}

__global__ __launch_bounds__(TPB, 1)
void nmm_kernel(const float* __restrict__ params,
                const float* __restrict__ C,
                const float* __restrict__ y0,
                float* __restrict__ out,
                int num_steps)
{
    // 3-buffer delayed-E rotation: matvec at step s consumes registers
    // prefetched from ebuf[s%3] (during step s-1); tail of step s writes
    // E_{s+1} into ebuf[(s+2)%3] (prefetched during s+1, used at s+2).
    // => every STS->LDS crossing has a FULL STEP of slack, and the step
    // front (pointwise + whole matvec) has no barrier-dependent instrs:
    // the deferred-blocking BAR absorbs release latency + warp skew.
    __shared__ __align__(16) float ebuf[3][72];
    // Ping-pong output staging tiles (33-col pad: conflict-free).
    __shared__ float outbuf[2][NN][TILE + 1];

    const int tid  = threadIdx.x;
    const int lane = tid & 31;
    const int wid  = tid >> 5;
    const int r    = tid;                 // row owned by this thread (r < 68)

    const float tau_e = params[0], tau_i = params[1];
    const float c1 = params[2], c2 = params[3], c3 = params[4], c4 = params[5];
    const float c5 = params[6], P  = params[7], kE = params[8], kI = params[9];
    const float inv_te = 1.0f / tau_e;
    const float inv_ti = 1.0f / tau_i;
    const float ce = 1.0f - inv_te;
    const float ci = 1.0f - inv_ti;

    const float LOG2E = 1.4426950408889634f;
    const float AE = 1.3f, THR_E = 4.0f;
    const float AI = 2.0f, THR_I = 3.7f;
    const float aeL = AE * LOG2E;
    const float aiL = AI * LOG2E;
    const float S0E = 1.0f / (1.0f + expf(AE * THR_E));
    const float S0I = 1.0f / (1.0f + expf(AI * THR_I));

    // argE = [cE0 + mEc1*E + pEc2*I] + kconn*conn ; argI = cI0 + mIc3*E + pIc4*I
    const float cE0   = aeL * (THR_E - P);
    const float mEc1  = -aeL * c1;
    const float pEc2  =  aeL * c2;
    const float kconn = -aeL * c5;        // folded into crow below
    const float cI0   = aiL * THR_I;
    const float mIc3  = -aiL * c3;
    const float pIc4  =  aiL * c4;

    float E = 0.0f, I = 0.0f;
    u64 crow[34];                         // kconn * C[r,:], packed f32x2
    u64 ep[2 * NPRE];                     // E_prev for the CURRENT step (regs)

    if (r < NN) {
        E = y0[r];
        I = y0[NN + r];
        ebuf[0][r] = E;                   // steps 0 AND 1 both read E0
        ebuf[1][r] = E;
        const ulonglong2* cp = reinterpret_cast<const ulonglong2*>(C + r * NN);
        const u64 k2 = pack2(kconn, kconn);
        #pragma unroll
        for (int j = 0; j < 17; j++) {
            ulonglong2 c = cp[j];
            crow[2 * j]     = fmul2(c.x, k2);
            crow[2 * j + 1] = fmul2(c.y, k2);
        }
    }
    __syncthreads();

    if (r < NN) {                         // prologue prefetch for step 0
        const ulonglong2* eb = reinterpret_cast<const ulonglong2*>(ebuf[0]);
        #pragma unroll
        for (int j = 0; j < NPRE; j++) {
            ulonglong2 e = eb[j];
            ep[2 * j]     = e.x;
            ep[2 * j + 1] = e.y;
        }
    }

    // ---- one Euler step; PHI = s % 3 (compile-time), S = runtime step ----
#define STEP(PHI, S)                                                           \
    {                                                                          \
        if (r < NN) {                                                          \
            /* hoisted pointwise (depends only on own E, I registers) */       \
            const float gE = inv_te * (kE - E);                                \
            const float hE = fmaf(-gE, S0E, E * ce);                           \
            const float gI = inv_ti * (kI - I);                                \
            const float hI = fmaf(-gI, S0I, I * ci);                           \
            const float base_e = fmaf(mEc1, E, fmaf(pEc2, I, cE0));            \
            const float argI   = fmaf(mIc3, E, fmaf(pIc4, I, cI0));            \
            const float sIv = rcpa(1.0f + ex2a(argI));                         \
            const float In  = fmaf(gI, sIv, hI);                               \
            /* matvec: ALL operands in registers (no LDS on the front;   */    \
            /* summation pattern bit-identical to the validated R5 one)  */    \
            u64 a0 = pack2(base_e, 0.0f);   /* seed base_e into reduction */   \
            u64 a1 = 0ull, a2 = 0ull, a3 = 0ull;                               \
            _Pragma("unroll")                                                  \
            for (int j = 0; j < 17; j++) {                                     \
                if (j & 1) {                                                   \
                    a2 = ffma2(crow[2 * j],     ep[2 * j],     a2);            \
                    a3 = ffma2(crow[2 * j + 1], ep[2 * j + 1], a3);            \
                } else {                                                       \
                    a0 = ffma2(crow[2 * j],     ep[2 * j],     a0);            \
                    a1 = ffma2(crow[2 * j + 1], ep[2 * j + 1], a1);            \
                }                                                              \
            }                                                                  \
            /* prefetch NEXT step's E_prev (written at tail of S-1,      */    \
            /* ordered by this step's entry barrier; consumers are a     */    \
            /* full step away). WAR on ep is handled by ptxas ordering.  */    \
            {                                                                  \
                const ulonglong2* ebn =                                        \
                    reinterpret_cast<const ulonglong2*>(ebuf[((PHI) + 1) % 3]);\
                _Pragma("unroll")                                              \
                for (int j = 0; j < NPRE; j++) {                               \
                    ulonglong2 e = ebn[j];                                     \
                    ep[2 * j]     = e.x;                                       \
                    ep[2 * j + 1] = e.y;                                       \
                }                                                              \
            }                                                                  \
            /* reduce (base_e already inside) + sigmoid tail */                \
            u64 sv = fadd2(fadd2(a0, a1), fadd2(a2, a3));                      \
            float sx, sy;                                                      \
            unpk(sv, sx, sy);                                                  \
            const float argE = sx + sy;                                        \
            const float sEv  = rcpa(1.0f + ex2a(argE));                        \
            const float En   = fmaf(gE, sEv, hE);                              \
            ebuf[((PHI) + 2) % 3][r] = En;     /* E_{S+1}, read at step S+2 */ \
            outbuf[((S) >> 5) & 1][r][(S) & (TILE - 1)] = En - In;             \
            E = En;                                                            \
            I = In;                                                            \
        }                                                                      \
        __syncthreads();                                                       \
        /* warp 3 (otherwise idle): flush previous tile, 17 rows per step   */ \
        /* over the 4 steps after tile completion — hidden under step time. */ \
        if (wid == 3) {                                                        \
            const int fk = (S) & 31;                                           \
            if (fk < 4 && (S) >= 32) {                                         \
                const int fb    = ((S) >> 5) - 1;                              \
                const int ftile = fb & 1;                                      \
                const int fbase = fb << 5;                                     \
                _Pragma("unroll")                                              \
                for (int i = 0; i < 17; i++) {                                 \
                    const int row = fk * 17 + i;                               \
                    out[row * num_steps + fbase + lane] =                      \
                        outbuf[ftile][row][lane];                              \
                }                                                              \
            }                                                                  \
        }                                                                      \
    }

    int s = 0;
    for (; s + 3 <= num_steps; s += 3) {
        STEP(0, s)
        STEP(1, s + 1)
        STEP(2, s + 2)
    }
    if (s < num_steps) { STEP(0, s) s++; }
    if (s < num_steps) { STEP(1, s) s++; }
#undef STEP

    // Epilogue: flush whatever the in-loop warp-3 flush couldn't cover
    // (last complete tile whose flush window fell off the end + partial tile).
    int start;
    if (num_steps < 36) start = 0;
    else                start = (((num_steps - 36) >> 5) << 5) + 32;
    for (int tb = start; tb < num_steps; tb += 32) {
        const int ftile = (tb >> 5) & 1;
        const int cnt   = num_steps - tb < 32 ? num_steps - tb : 32;
        for (int row = wid; row < NN; row += 4)
            if (lane < cnt)
                out[row * num_steps + tb + lane] = outbuf[ftile][row][lane];
    }
}

extern "C" void kernel_launch(void* const* d_in, const int* in_sizes, int n_in,
                              void* d_out, int out_size)
{
    const float* params = (const float*)d_in[0];
    const float* Cjk    = (const float*)d_in[1];
    const float* y0     = (const float*)d_in[2];
    // d_in[3] = Djk: unused by the reference computation.
    float* out = (float*)d_out;
    const int num_steps = out_size / NN;   // out is (N=68, num_steps)
    nmm_kernel<<<1, TPB>>>(params, Cjk, y0, out, num_steps);
}

// round 7
// speedup vs baseline: 1.8851x; 1.0592x over previous
#include <cuda_runtime.h>
#include <math.h>

#define NN    68
#define TPB   128
#define TILE  32

typedef unsigned long long u64;

// Packed f32x2 ops (Blackwell) — only reachable via PTX.
__device__ __forceinline__ u64 ffma2(u64 a, u64 b, u64 c) {
    u64 d;
    asm("fma.rn.f32x2 %0, %1, %2, %3;" : "=l"(d) : "l"(a), "l"(b), "l"(c));
    return d;
}
__device__ __forceinline__ u64 fadd2(u64 a, u64 b) {
    u64 d;
    asm("add.rn.f32x2 %0, %1, %2;" : "=l"(d) : "l"(a), "l"(b));
    return d;
}
__device__ __forceinline__ u64 fmul2(u64 a, u64 b) {
    u64 d;
    asm("mul.rn.f32x2 %0, %1, %2;" : "=l"(d) : "l"(a), "l"(b));
    return d;
}
__device__ __forceinline__ void unpk(u64 v, float &x, float &y) {
    asm("mov.b64 {%0, %1}, %2;" : "=f"(x), "=f"(y) : "l"(v));
}
__device__ __forceinline__ u64 pack2(float x, float y) {
    u64 v;
    asm("mov.b64 %0, {%1, %2};" : "=l"(v) : "f"(x), "f"(y));
    return v;
}
// MUFU fast paths (~1e-7 rel err; validated 1.3e-6 final over 200k steps).
__device__ __forceinline__ float ex2a(float x) {
    float y; asm("ex2.approx.f32 %0, %1;" : "=f"(y) : "f"(x)); return y;
}
__device__ __forceinline__ float rcpa(float x) {
    float y; asm("rcp.approx.f32 %0, %1;" : "=f"(y) : "f"(x)); return y;
}

__global__ __launch_bounds__(TPB, 1)
void nmm_kernel(const float* __restrict__ params,
                const float* __restrict__ C,
                const float* __restrict__ y0,
                float* __restrict__ out,
                int num_steps)
{
    // 4-slot ring: E_t lives in ebuf[t & 3]. Block k runs iterations
    // {2k, 2k+1}: reads E_{2k-1} (slot (P+3)&3) and E_{2k} (slot P), both
    // published by block k-1; writes E_{2k+1} (slot (P+1)&3) and E_{2k+2}
    // (slot (P+2)&3). All four slots distinct => ONE barrier per block
    // orders every cross-thread crossing. The one-step coupling delay is
    // exactly what makes 2 steps/barrier legal.
    __shared__ __align__(16) float ebuf[4][72];
    // Ping-pong output staging tiles (33-col pad: conflict-free).
    __shared__ float outbuf[2][NN][TILE + 1];

    const int tid  = threadIdx.x;
    const int lane = tid & 31;
    const int wid  = tid >> 5;
    const int r    = tid;                 // row owned by this thread (r < 68)

    const float tau_e = params[0], tau_i = params[1];
    const float c1 = params[2], c2 = params[3], c3 = params[4], c4 = params[5];
    const float c5 = params[6], P  = params[7], kE = params[8], kI = params[9];
    const float inv_te = 1.0f / tau_e;
    const float inv_ti = 1.0f / tau_i;
    const float ce = 1.0f - inv_te;
    const float ci = 1.0f - inv_ti;

    const float LOG2E = 1.4426950408889634f;
    const float AE = 1.3f, THR_E = 4.0f;
    const float AI = 2.0f, THR_I = 3.7f;
    const float aeL = AE * LOG2E;
    const float aiL = AI * LOG2E;
    const float S0E = 1.0f / (1.0f + expf(AE * THR_E));
    const float S0I = 1.0f / (1.0f + expf(AI * THR_I));

    // argE = [cE0 + mEc1*E + pEc2*I] + kconn*conn ; argI = cI0 + mIc3*E + pIc4*I
    const float cE0   = aeL * (THR_E - P);
    const float mEc1  = -aeL * c1;
    const float pEc2  =  aeL * c2;
    const float kconn = -aeL * c5;        // folded into crow below
    const float cI0   = aiL * THR_I;
    const float mIc3  = -aiL * c3;
    const float pIc4  =  aiL * c4;

    float E = 0.0f, I = 0.0f;
    u64 crow[34];                         // kconn * C[r,:], packed f32x2

    if (r < NN) {
        E = y0[r];
        I = y0[NN + r];
        ebuf[3][r] = E;                   // E_{-1} := E_0 (reference carry)
        ebuf[0][r] = E;                   // E_0
        const ulonglong2* cp = reinterpret_cast<const ulonglong2*>(C + r * NN);
        const u64 k2 = pack2(kconn, kconn);
        #pragma unroll
        for (int j = 0; j < 17; j++) {
            ulonglong2 c = cp[j];
            crow[2 * j]     = fmul2(c.x, k2);
            crow[2 * j + 1] = fmul2(c.y, k2);
        }
    }
    __syncthreads();

    // Warp-3 flush of one step's column (17 rows) if step X is in a window.
#define FLUSH_STEP(X)                                                          \
    {                                                                          \
        const int fk = (X) & 31;                                               \
        if (fk < 4 && (X) >= 32) {                                             \
            const int fb    = ((X) >> 5) - 1;                                  \
            const int ftile = fb & 1;                                          \
            const int fbase = fb << 5;                                         \
            _Pragma("unroll")                                                  \
            for (int i = 0; i < 17; i++) {                                     \
                const int row = fk * 17 + i;                                   \
                out[row * num_steps + fbase + lane] = outbuf[ftile][row][lane];\
            }                                                                  \
        }                                                                      \
    }

    // ---- one block = 2 Euler steps (S even), ONE barrier ----
    // P = S % 4 (compile-time 0 or 2 in the main loop).
#define BLOCK(PAR, S)                                                          \
    {                                                                          \
        if (r < NN) {                                                          \
            /* pointwise-A from (E, I) = state at iteration S */               \
            const float gEa = inv_te * (kE - E);                               \
            const float hEa = fmaf(-gEa, S0E, E * ce);                         \
            const float gIa = inv_ti * (kI - I);                               \
            const float hIa = fmaf(-gIa, S0I, I * ci);                         \
            const float base_ea = fmaf(mEc1, E, fmaf(pEc2, I, cE0));           \
            const float argIa   = fmaf(mIc3, E, fmaf(pIc4, I, cI0));           \
            const float sIa = rcpa(1.0f + ex2a(argIa));                        \
            const float Ina = fmaf(gIa, sIa, hIa);                             \
            /* matvec-A over E_{S-1}; summation pattern identical to R6 */     \
            const ulonglong2* ea =                                             \
                reinterpret_cast<const ulonglong2*>(ebuf[((PAR) + 3) & 3]);    \
            u64 a0 = pack2(base_ea, 0.0f);                                     \
            u64 a1 = 0ull, a2 = 0ull, a3 = 0ull;                               \
            _Pragma("unroll")                                                  \
            for (int j = 0; j < 17; j++) {                                     \
                ulonglong2 e = ea[j];                                          \
                if (j & 1) {                                                   \
                    a2 = ffma2(crow[2 * j],     e.x, a2);                      \
                    a3 = ffma2(crow[2 * j + 1], e.y, a3);                      \
                } else {                                                       \
                    a0 = ffma2(crow[2 * j],     e.x, a0);                      \
                    a1 = ffma2(crow[2 * j + 1], e.y, a1);                      \
                }                                                              \
            }                                                                  \
            /* matvec-B over E_S — independent of tail-A: its FFMA2 issue  */  \
            /* stream absorbs tail-A's MUFU/reduce latency.                */  \
            const ulonglong2* eb2 =                                            \
                reinterpret_cast<const ulonglong2*>(ebuf[(PAR)]);              \
            u64 b0 = 0ull, b1 = 0ull, b2 = 0ull, b3 = 0ull;                    \
            _Pragma("unroll")                                                  \
            for (int j = 0; j < 17; j++) {                                     \
                ulonglong2 e = eb2[j];                                         \
                if (j & 1) {                                                   \
                    b2 = ffma2(crow[2 * j],     e.x, b2);                      \
                    b3 = ffma2(crow[2 * j + 1], e.y, b3);                      \
                } else {                                                       \
                    b0 = ffma2(crow[2 * j],     e.x, b0);                      \
                    b1 = ffma2(crow[2 * j + 1], e.y, b1);                      \
                }                                                              \
            }                                                                  \
            /* tail-A */                                                       \
            u64 sv = fadd2(fadd2(a0, a1), fadd2(a2, a3));                      \
            float sx, sy;                                                      \
            unpk(sv, sx, sy);                                                  \
            const float argEa = sx + sy;                                       \
            const float sEa   = rcpa(1.0f + ex2a(argEa));                      \
            const float Ena   = fmaf(gEa, sEa, hEa);                           \
            ebuf[((PAR) + 1) & 3][r] = Ena;        /* publish E_{S+1} */       \
            outbuf[((S) >> 5) & 1][r][(S) & (TILE - 1)] = Ena - Ina;           \
            /* pointwise-B from (Ena, Ina) */                                  \
            const float gEb = inv_te * (kE - Ena);                             \
            const float hEb = fmaf(-gEb, S0E, Ena * ce);                       \
            const float gIb = inv_ti * (kI - Ina);                             \
            const float hIb = fmaf(-gIb, S0I, Ina * ci);                       \
            const float base_eb = fmaf(mEc1, Ena, fmaf(pEc2, Ina, cE0));       \
            const float argIb   = fmaf(mIc3, Ena, fmaf(pIc4, Ina, cI0));       \
            const float sIb = rcpa(1.0f + ex2a(argIb));                        \
            const float Inb = fmaf(gIb, sIb, hIb);                             \
            /* tail-B (reduce-B already retired under tail-A) */               \
            u64 tv = fadd2(fadd2(b0, b1), fadd2(b2, b3));                      \
            float tx, ty;                                                      \
            unpk(tv, tx, ty);                                                  \
            const float argEb = (tx + ty) + base_eb;                           \
            const float sEb   = rcpa(1.0f + ex2a(argEb));                      \
            const float Enb   = fmaf(gEb, sEb, hEb);                           \
            ebuf[((PAR) + 2) & 3][r] = Enb;        /* publish E_{S+2} */       \
            outbuf[(((S) + 1) >> 5) & 1][r][((S) + 1) & (TILE - 1)] =          \
                Enb - Inb;                                                     \
            E = Enb;                                                           \
            I = Inb;                                                           \
        }                                                                      \
        __syncthreads();                                                       \
        if (wid == 3) {                                                        \
            FLUSH_STEP(S)                                                      \
            FLUSH_STEP((S) + 1)                                                \
        }                                                                      \
    }

    int s = 0;
    for (; s + 4 <= num_steps; s += 4) {
        BLOCK(0, s)
        BLOCK(2, s + 2)
    }
    if (s + 2 <= num_steps) {   // here s % 4 == 0
        BLOCK(0, s)
        s += 2;
    }
    if (s < num_steps) {        // odd tail: one generic step, runtime slots
        if (r < NN) {
            const float gE = inv_te * (kE - E);
            const float hE = fmaf(-gE, S0E, E * ce);
            const float gI = inv_ti * (kI - I);
            const float hI = fmaf(-gI, S0I, I * ci);
            const float base_e = fmaf(mEc1, E, fmaf(pEc2, I, cE0));
            const float argI   = fmaf(mIc3, E, fmaf(pIc4, I, cI0));
            const float sIv = rcpa(1.0f + ex2a(argI));
            const float In  = fmaf(gI, sIv, hI);
            const ulonglong2* ea =
                reinterpret_cast<const ulonglong2*>(ebuf[(s + 3) & 3]);
            u64 a0 = pack2(base_e, 0.0f);
            u64 a1 = 0ull, a2 = 0ull, a3 = 0ull;
            #pragma unroll
            for (int j = 0; j < 17; j++) {
                ulonglong2 e = ea[j];
                if (j & 1) {
                    a2 = ffma2(crow[2 * j],     e.x, a2);
                    a3 = ffma2(crow[2 * j + 1], e.y, a3);
                } else {
                    a0 = ffma2(crow[2 * j],     e.x, a0);
                    a1 = ffma2(crow[2 * j + 1], e.y, a1);
                }
            }
            u64 sv = fadd2(fadd2(a0, a1), fadd2(a2, a3));
            float sx, sy;
            unpk(sv, sx, sy);
            const float argE = sx + sy;
            const float sEv  = rcpa(1.0f + ex2a(argE));
            const float En   = fmaf(gE, sEv, hE);
            outbuf[(s >> 5) & 1][r][s & (TILE - 1)] = En - In;
        }
        __syncthreads();
        s++;
    }
#undef BLOCK
#undef FLUSH_STEP

    // Epilogue: flush tiles the in-loop warp-3 flush couldn't cover
    // (last complete tile whose flush window fell off the end + partial tile).
    int start;
    if (num_steps < 36) start = 0;
    else                start = (((num_steps - 36) >> 5) << 5) + 32;
    for (int tb = start; tb < num_steps; tb += 32) {
        const int ftile = (tb >> 5) & 1;
        const int cnt   = num_steps - tb < 32 ? num_steps - tb : 32;
        for (int row = wid; row < NN; row += 4)
            if (lane < cnt)
                out[row * num_steps + tb + lane] = outbuf[ftile][row][lane];
    }
}

extern "C" void kernel_launch(void* const* d_in, const int* in_sizes, int n_in,
                              void* d_out, int out_size)
{
    const float* params = (const float*)d_in[0];
    const float* Cjk    = (const float*)d_in[1];
    const float* y0     = (const float*)d_in[2];
    // d_in[3] = Djk: unused by the reference computation.
    float* out = (float*)d_out;
    const int num_steps = out_size / NN;   // out is (N=68, num_steps)
    nmm_kernel<<<1, TPB>>>(params, Cjk, y0, out, num_steps);
}